// round 3
// baseline (speedup 1.0000x reference)
#include <cuda_runtime.h>

#define NNODES 50000
#define NEDGES 500000
#define NGRAPH 64
#define FDIM   128      // H*D
#define NCLS   5
#define SLOPE  0.2f

// ---------------- scratch (device globals; no allocations allowed) ----------
__device__ float g_h[(size_t)NNODES * FDIM];     // per-layer GEMM output
__device__ float g_x[(size_t)NNODES * FDIM];     // per-layer aggregated (relu) output
__device__ float g_asrc[NNODES * 2];
__device__ float g_adst[NNODES * 2];
__device__ int   g_count[NNODES];
__device__ int   g_rowptr[NNODES + 1];
__device__ int   g_pos[NNODES];
__device__ int   g_srcsorted[NEDGES];
__device__ float g_pool[NGRAPH * FDIM];
__device__ int   g_cnt[NGRAPH];
__device__ int   g_is64;                          // 1 if edge_index/batch are int64

// ---------------- dtype detection (int64 vs int32 indices) ------------------
__global__ void detect_kernel(const void* ei_raw) {
    // If data is int64 (values < 2^31), every odd 32-bit word is 0.
    // If data is int32 (random node ids), odd words are almost never 0.
    __shared__ int zeros;
    if (threadIdx.x == 0) zeros = 0;
    __syncthreads();
    const int* w = (const int*)ei_raw;
    int local = 0;
    for (int i = threadIdx.x; i < 1024; i += blockDim.x) {
        if (w[2 * i + 1] == 0) local++;
    }
    atomicAdd(&zeros, local);
    __syncthreads();
    if (threadIdx.x == 0) g_is64 = (zeros > 900) ? 1 : 0;
}

__device__ __forceinline__ int load_idx(const void* p, long long i) {
    if (g_is64) return (int)((const long long*)p)[i];
    return ((const int*)p)[i];
}

// ---------------- zero scratch ----------------------------------------------
__global__ void zero_kernel() {
    int i = blockIdx.x * blockDim.x + threadIdx.x;
    if (i < NNODES) g_count[i] = 0;
    if (i < NGRAPH * FDIM) g_pool[i] = 0.f;
    if (i < NGRAPH) g_cnt[i] = 0;
}

// ---------------- CSR build --------------------------------------------------
__global__ void hist_kernel(const void* ei) {
    int e = blockIdx.x * blockDim.x + threadIdx.x;
    if (e >= NEDGES) return;
    int d = load_idx(ei, (long long)NEDGES + e);
    atomicAdd(&g_count[d], 1);
}

#define SCAN_T 1024
#define SCAN_CH ((NNODES + SCAN_T - 1) / SCAN_T)
__global__ void scan_kernel() {
    __shared__ int sums[SCAN_T];
    int t = threadIdx.x;
    int base = t * SCAN_CH;
    int s = 0;
    for (int i = 0; i < SCAN_CH; i++) {
        int idx = base + i;
        if (idx < NNODES) s += g_count[idx];
    }
    sums[t] = s;
    __syncthreads();
    // Hillis-Steele inclusive scan
    for (int off = 1; off < SCAN_T; off <<= 1) {
        int v = sums[t];
        int u = (t >= off) ? sums[t - off] : 0;
        __syncthreads();
        sums[t] = v + u;
        __syncthreads();
    }
    int run = (t == 0) ? 0 : sums[t - 1];
    for (int i = 0; i < SCAN_CH; i++) {
        int idx = base + i;
        if (idx < NNODES) {
            g_rowptr[idx] = run;
            g_pos[idx] = run;
            run += g_count[idx];
        }
    }
    if (t == SCAN_T - 1) g_rowptr[NNODES] = run;
}

__global__ void scatter_kernel(const void* ei) {
    int e = blockIdx.x * blockDim.x + threadIdx.x;
    if (e >= NEDGES) return;
    int s = load_idx(ei, e);
    int d = load_idx(ei, (long long)NEDGES + e);
    int p = atomicAdd(&g_pos[d], 1);
    g_srcsorted[p] = s;
}

// ---------------- GEMM: h = X @ W  (X: [N,K], W: [K,128]) --------------------
// 64-node tile per block, 256 threads, each thread: 8 nodes x 4 cols.
__global__ void gemm_kernel(const float* __restrict__ Xin, int K,
                            const float* __restrict__ W) {
    __shared__ float ws[8][132];
    __shared__ float xs[64][9];
    const float* X = Xin ? Xin : g_x;
    int tid = threadIdx.x;
    int n0 = blockIdx.x * 64;
    int j = (tid & 31) * 4;
    int warp = tid >> 5;

    float4 acc[8];
#pragma unroll
    for (int r = 0; r < 8; r++) acc[r] = make_float4(0.f, 0.f, 0.f, 0.f);

    for (int k0 = 0; k0 < K; k0 += 8) {
        // stage W tile [8 x 128]
        {
            int kk = tid >> 5, cc = (tid & 31) * 4;
            float4 wv = make_float4(0.f, 0.f, 0.f, 0.f);
            if (k0 + kk < K) wv = *(const float4*)&W[(size_t)(k0 + kk) * FDIM + cc];
            ws[kk][cc] = wv.x; ws[kk][cc + 1] = wv.y;
            ws[kk][cc + 2] = wv.z; ws[kk][cc + 3] = wv.w;
        }
        // stage X tile [64 x 8]
#pragma unroll
        for (int q = 0; q < 2; q++) {
            int e2 = tid * 2 + q;
            int n = e2 >> 3, k = e2 & 7;
            float v = 0.f;
            if (n0 + n < NNODES && k0 + k < K)
                v = X[(size_t)(n0 + n) * K + k0 + k];
            xs[n][k] = v;
        }
        __syncthreads();
#pragma unroll
        for (int kk = 0; kk < 8; kk++) {
            float4 wv = *(const float4*)&ws[kk][j];
#pragma unroll
            for (int r = 0; r < 8; r++) {
                float xv = xs[warp * 8 + r][kk];
                acc[r].x = fmaf(wv.x, xv, acc[r].x);
                acc[r].y = fmaf(wv.y, xv, acc[r].y);
                acc[r].z = fmaf(wv.z, xv, acc[r].z);
                acc[r].w = fmaf(wv.w, xv, acc[r].w);
            }
        }
        __syncthreads();
    }
#pragma unroll
    for (int r = 0; r < 8; r++) {
        int n = n0 + warp * 8 + r;
        if (n < NNODES) *(float4*)&g_h[(size_t)n * FDIM + j] = acc[r];
    }
}

// ---------------- attention logits per node ----------------------------------
// asrc[n][h] = <h[n,h,:], a_src[h,:]> ; adst similarly. One warp per node.
__global__ void alpha_kernel(const float* __restrict__ Asrc,
                             const float* __restrict__ Adst) {
    int gw = (blockIdx.x * blockDim.x + threadIdx.x) >> 5;
    int lane = threadIdx.x & 31;
    if (gw >= NNODES) return;
    int f = lane * 4;
    float4 hv = *(const float4*)&g_h[(size_t)gw * FDIM + f];
    float4 as = *(const float4*)&Asrc[f];   // [H,D] flat == [128]
    float4 ad = *(const float4*)&Adst[f];
    float vs = hv.x * as.x + hv.y * as.y + hv.z * as.z + hv.w * as.w;
    float vd = hv.x * ad.x + hv.y * ad.y + hv.z * ad.z + hv.w * ad.w;
#pragma unroll
    for (int o = 8; o >= 1; o >>= 1) {
        vs += __shfl_down_sync(0xffffffffu, vs, o, 16);
        vd += __shfl_down_sync(0xffffffffu, vd, o, 16);
    }
    if ((lane & 15) == 0) {
        int h = lane >> 4;
        g_asrc[gw * 2 + h] = vs;
        g_adst[gw * 2 + h] = vd;
    }
}

// ---------------- aggregation: online segment softmax + weighted sum ---------
// One warp per destination node; lanes 0-15 = head 0, 16-31 = head 1.
// Writes g_x (device symbol) directly — passing &g_x from host is invalid!
__global__ void agg_kernel(const float* __restrict__ B) {
    int n = (blockIdx.x * blockDim.x + threadIdx.x) >> 5;
    int lane = threadIdx.x & 31;
    if (n >= NNODES) return;
    int f = lane * 4;
    int head = lane >> 4;
    float ad = g_adst[n * 2 + head];
    int beg = g_rowptr[n], end = g_rowptr[n + 1];

    float m = -3.0e38f, s = 0.f;
    float4 acc = make_float4(0.f, 0.f, 0.f, 0.f);
    for (int i = beg; i < end; i++) {
        int src = g_srcsorted[i];
        float ev = g_asrc[src * 2 + head] + ad;
        ev = (ev > 0.f) ? ev : SLOPE * ev;
        float nm = fmaxf(m, ev);
        float sc = __expf(m - nm);
        float p = __expf(ev - nm);
        s = s * sc + p;
        float4 hv = *(const float4*)&g_h[(size_t)src * FDIM + f];
        acc.x = acc.x * sc + p * hv.x;
        acc.y = acc.y * sc + p * hv.y;
        acc.z = acc.z * sc + p * hv.z;
        acc.w = acc.w * sc + p * hv.w;
        m = nm;
    }
    float inv = 1.f / (s + 1e-16f);
    float4 o;
    o.x = fmaxf(acc.x * inv + B[f + 0], 0.f);
    o.y = fmaxf(acc.y * inv + B[f + 1], 0.f);
    o.z = fmaxf(acc.z * inv + B[f + 2], 0.f);
    o.w = fmaxf(acc.w * inv + B[f + 3], 0.f);
    *(float4*)&g_x[(size_t)n * FDIM + f] = o;
}

// ---------------- global mean pool (sum + count) ------------------------------
__global__ void pool_kernel(const void* batch) {
    int idx = blockIdx.x * blockDim.x + threadIdx.x;
    int n = idx >> 5;
    int lane = idx & 31;
    if (n >= NNODES) return;
    int b = load_idx(batch, n);
    int f = lane * 4;
    float4 v = *(const float4*)&g_x[(size_t)n * FDIM + f];
    atomicAdd(&g_pool[b * FDIM + f + 0], v.x);
    atomicAdd(&g_pool[b * FDIM + f + 1], v.y);
    atomicAdd(&g_pool[b * FDIM + f + 2], v.z);
    atomicAdd(&g_pool[b * FDIM + f + 3], v.w);
    if (lane == 0) atomicAdd(&g_cnt[b], 1);
}

// ---------------- final linear + sigmoid -------------------------------------
__global__ void final_kernel(const float* __restrict__ LW,
                             const float* __restrict__ LB,
                             float* __restrict__ out) {
    int t = threadIdx.x;
    if (t >= NGRAPH * NCLS) return;
    int g = t / NCLS, c = t % NCLS;
    float cnt = (float)g_cnt[g];
    if (cnt < 1.f) cnt = 1.f;
    float sum = 0.f;
    for (int k = 0; k < FDIM; k++)
        sum = fmaf(g_pool[g * FDIM + k], LW[k * NCLS + c], sum);
    float z = sum / cnt + LB[c];
    out[t] = 1.f / (1.f + expf(-z));
}

// ---------------- launch ------------------------------------------------------
extern "C" void kernel_launch(void* const* d_in, const int* in_sizes, int n_in,
                              void* d_out, int out_size) {
    const float* x = (const float*)d_in[0];
    const void* ei = d_in[1];
    const void* batch = d_in[2];
    const float* W[4]  = {(const float*)d_in[3],  (const float*)d_in[7],
                          (const float*)d_in[11], (const float*)d_in[15]};
    const float* As[4] = {(const float*)d_in[4],  (const float*)d_in[8],
                          (const float*)d_in[12], (const float*)d_in[16]};
    const float* Ad[4] = {(const float*)d_in[5],  (const float*)d_in[9],
                          (const float*)d_in[13], (const float*)d_in[17]};
    const float* Bb[4] = {(const float*)d_in[6],  (const float*)d_in[10],
                          (const float*)d_in[14], (const float*)d_in[18]};
    const float* LW = (const float*)d_in[19];
    const float* LB = (const float*)d_in[20];
    float* out = (float*)d_out;

    detect_kernel<<<1, 256>>>(ei);
    zero_kernel<<<(NNODES + 255) / 256, 256>>>();
    hist_kernel<<<(NEDGES + 255) / 256, 256>>>(ei);
    scan_kernel<<<1, SCAN_T>>>();
    scatter_kernel<<<(NEDGES + 255) / 256, 256>>>(ei);

    int gemm_blocks = (NNODES + 63) / 64;
    int warp_blocks = (NNODES * 32 + 255) / 256;
    for (int l = 0; l < 4; l++) {
        const float* xin = (l == 0) ? x : nullptr;   // nullptr -> use g_x
        int K = (l == 0) ? 4 : FDIM;
        gemm_kernel<<<gemm_blocks, 256>>>(xin, K, W[l]);
        alpha_kernel<<<warp_blocks, 256>>>(As[l], Ad[l]);
        agg_kernel<<<warp_blocks, 256>>>(Bb[l]);
    }
    pool_kernel<<<warp_blocks, 256>>>(batch);
    final_kernel<<<1, NGRAPH * NCLS>>>(LW, LB, out);
}

// round 4
// speedup vs baseline: 1.1043x; 1.1043x over previous
#include <cuda_runtime.h>

#define NNODES 50000
#define NEDGES 500000
#define NGRAPH 64
#define FDIM   128      // H*D
#define NCLS   5
#define SLOPE  0.2f
#define NBLK   ((NNODES + 1023) / 1024)   // 49 scan blocks

// ---------------- scratch (device globals; no allocations allowed) ----------
__device__ float g_h[(size_t)NNODES * FDIM];     // per-layer GEMM output
__device__ float g_x[(size_t)NNODES * FDIM];     // per-layer aggregated output
__device__ float g_asrc[NNODES * 2];
__device__ float g_adst[NNODES * 2];
__device__ int   g_count[NNODES];
__device__ int   g_rowptr[NNODES + 1];
__device__ int   g_pos[NNODES];
__device__ int   g_bsum[64];
__device__ int   g_srcsorted[NEDGES];
__device__ float g_pool[NGRAPH * FDIM];
__device__ int   g_cnt[NGRAPH];
__device__ int   g_is64;                          // 1 if edge_index/batch are int64

// ---------------- dtype detection (int64 vs int32 indices) ------------------
__global__ void detect_kernel(const void* ei_raw) {
    __shared__ int zeros;
    if (threadIdx.x == 0) zeros = 0;
    __syncthreads();
    const int* w = (const int*)ei_raw;
    int local = 0;
    for (int i = threadIdx.x; i < 1024; i += blockDim.x) {
        if (w[2 * i + 1] == 0) local++;
    }
    atomicAdd(&zeros, local);
    __syncthreads();
    if (threadIdx.x == 0) g_is64 = (zeros > 900) ? 1 : 0;
}

__device__ __forceinline__ int load_idx(const void* p, long long i) {
    if (g_is64) return (int)((const long long*)p)[i];
    return ((const int*)p)[i];
}

// ---------------- zero scratch ----------------------------------------------
__global__ void zero_kernel() {
    int i = blockIdx.x * blockDim.x + threadIdx.x;
    if (i < NNODES) g_count[i] = 0;
    if (i < NGRAPH * FDIM) g_pool[i] = 0.f;
    if (i < NGRAPH) g_cnt[i] = 0;
}

// ---------------- CSR build --------------------------------------------------
__global__ void hist_kernel(const void* ei) {
    int e = blockIdx.x * blockDim.x + threadIdx.x;
    if (e >= NEDGES) return;
    int d = load_idx(ei, (long long)NEDGES + e);
    atomicAdd(&g_count[d], 1);
}

// Multi-block scan: A) per-block scan, B) scan of 49 block sums, C) add offsets.
__global__ void scanA_kernel() {
    int t = threadIdx.x;                       // 256 threads, 4 elems each
    int base = blockIdx.x * 1024 + t * 4;
    int c0 = 0, c1 = 0, c2 = 0, c3 = 0;
    if (base + 0 < NNODES) c0 = g_count[base + 0];
    if (base + 1 < NNODES) c1 = g_count[base + 1];
    if (base + 2 < NNODES) c2 = g_count[base + 2];
    if (base + 3 < NNODES) c3 = g_count[base + 3];
    int s = c0 + c1 + c2 + c3;
    int lane = t & 31, warp = t >> 5;
    int incl = s;
#pragma unroll
    for (int o = 1; o < 32; o <<= 1) {
        int u = __shfl_up_sync(0xffffffffu, incl, o);
        if (lane >= o) incl += u;
    }
    __shared__ int wtot[8];
    if (lane == 31) wtot[warp] = incl;
    __syncthreads();
    if (t == 0) {
        int r = 0;
#pragma unroll
        for (int w = 0; w < 8; w++) { int v = wtot[w]; wtot[w] = r; r += v; }
        g_bsum[blockIdx.x] = r;
    }
    __syncthreads();
    int excl = incl - s + wtot[warp];
    if (base + 0 < NNODES) g_rowptr[base + 0] = excl;
    if (base + 1 < NNODES) g_rowptr[base + 1] = excl + c0;
    if (base + 2 < NNODES) g_rowptr[base + 2] = excl + c0 + c1;
    if (base + 3 < NNODES) g_rowptr[base + 3] = excl + c0 + c1 + c2;
}

__global__ void scanB_kernel() {                // 64 threads, scan 49 sums
    int t = threadIdx.x;
    int v = (t < NBLK) ? g_bsum[t] : 0;
    int lane = t & 31, warp = t >> 5;
    int incl = v;
#pragma unroll
    for (int o = 1; o < 32; o <<= 1) {
        int u = __shfl_up_sync(0xffffffffu, incl, o);
        if (lane >= o) incl += u;
    }
    __shared__ int wt[2];
    if (lane == 31) wt[warp] = incl;
    __syncthreads();
    int add = (warp == 1) ? wt[0] : 0;
    int excl = incl - v + add;
    if (t < NBLK) g_bsum[t] = excl;
}

__global__ void scanC_kernel() {
    int i = blockIdx.x * blockDim.x + threadIdx.x;
    if (i < NNODES) {
        int r = g_rowptr[i] + g_bsum[i >> 10];
        g_rowptr[i] = r;
        g_pos[i] = r;
    }
    if (i == 0) g_rowptr[NNODES] = NEDGES;
}

__global__ void scatter_kernel(const void* ei) {
    int e = blockIdx.x * blockDim.x + threadIdx.x;
    if (e >= NEDGES) return;
    int s = load_idx(ei, e);
    int d = load_idx(ei, (long long)NEDGES + e);
    int p = atomicAdd(&g_pos[d], 1);
    g_srcsorted[p] = s;
}

// ---------------- GEMM + fused attention logits ------------------------------
// h = X @ W  (X: [N,K], W: [K,128]); epilogue computes per-node, per-head
// dot products with a_src/a_dst (half-warp shfl reduction).
__global__ void gemm_kernel(const float* __restrict__ Xin, int K,
                            const float* __restrict__ W,
                            const float* __restrict__ Asrc,
                            const float* __restrict__ Adst) {
    __shared__ float ws[8][132];
    __shared__ float xs[64][8];
    const float* X = Xin ? Xin : g_x;
    int tid = threadIdx.x;
    int n0 = blockIdx.x * 64;
    int lane = tid & 31;
    int j = lane * 4;
    int warp = tid >> 5;

    float4 acc[8];
#pragma unroll
    for (int r = 0; r < 8; r++) acc[r] = make_float4(0.f, 0.f, 0.f, 0.f);

    for (int k0 = 0; k0 < K; k0 += 8) {
        // stage W tile [8 x 128]
        {
            int kk = tid >> 5, cc = (tid & 31) * 4;
            float4 wv = make_float4(0.f, 0.f, 0.f, 0.f);
            if (k0 + kk < K) wv = *(const float4*)&W[(size_t)(k0 + kk) * FDIM + cc];
            ws[kk][cc] = wv.x; ws[kk][cc + 1] = wv.y;
            ws[kk][cc + 2] = wv.z; ws[kk][cc + 3] = wv.w;
        }
        // stage X tile [64 x 8]
#pragma unroll
        for (int q = 0; q < 2; q++) {
            int e2 = tid * 2 + q;
            int n = e2 >> 3, k = e2 & 7;
            float v = 0.f;
            if (n0 + n < NNODES && k0 + k < K)
                v = X[(size_t)(n0 + n) * K + k0 + k];
            xs[n][k] = v;
        }
        __syncthreads();
#pragma unroll
        for (int kk = 0; kk < 8; kk += 4) {
            float4 xv[8];
#pragma unroll
            for (int r = 0; r < 8; r++)
                xv[r] = *(const float4*)&xs[warp * 8 + r][kk];   // warp broadcast
#pragma unroll
            for (int q = 0; q < 4; q++) {
                float4 wv = *(const float4*)&ws[kk + q][j];
#pragma unroll
                for (int r = 0; r < 8; r++) {
                    float xq = (q == 0) ? xv[r].x : (q == 1) ? xv[r].y
                             : (q == 2) ? xv[r].z : xv[r].w;
                    acc[r].x = fmaf(wv.x, xq, acc[r].x);
                    acc[r].y = fmaf(wv.y, xq, acc[r].y);
                    acc[r].z = fmaf(wv.z, xq, acc[r].z);
                    acc[r].w = fmaf(wv.w, xq, acc[r].w);
                }
            }
        }
        __syncthreads();
    }

    // epilogue: store h + fused alpha logits
    float4 as = *(const float4*)&Asrc[j];
    float4 ad = *(const float4*)&Adst[j];
#pragma unroll
    for (int r = 0; r < 8; r++) {
        int n = n0 + warp * 8 + r;
        if (n < NNODES) *(float4*)&g_h[(size_t)n * FDIM + j] = acc[r];
        float vs = acc[r].x * as.x + acc[r].y * as.y + acc[r].z * as.z + acc[r].w * as.w;
        float vd = acc[r].x * ad.x + acc[r].y * ad.y + acc[r].z * ad.z + acc[r].w * ad.w;
#pragma unroll
        for (int o = 8; o >= 1; o >>= 1) {
            vs += __shfl_down_sync(0xffffffffu, vs, o, 16);
            vd += __shfl_down_sync(0xffffffffu, vd, o, 16);
        }
        if ((lane & 15) == 0 && n < NNODES) {
            int h = lane >> 4;
            g_asrc[n * 2 + h] = vs;
            g_adst[n * 2 + h] = vd;
        }
    }
}

// ---------------- aggregation: online segment softmax + weighted sum ---------
// One warp per destination node; lanes 0-15 = head 0, 16-31 = head 1.
// Software prefetch (depth 1) on the src-index / logit / h-row chain.
__global__ void agg_kernel(const float* __restrict__ B) {
    int n = (blockIdx.x * blockDim.x + threadIdx.x) >> 5;
    int lane = threadIdx.x & 31;
    if (n >= NNODES) return;
    int f = lane * 4;
    int head = lane >> 4;
    float ad = g_adst[n * 2 + head];
    int beg = g_rowptr[n], end = g_rowptr[n + 1];

    float m = -3.0e38f, s = 0.f;
    float4 acc = make_float4(0.f, 0.f, 0.f, 0.f);
    if (beg < end) {
        int src = g_srcsorted[beg];
        float ev = g_asrc[src * 2 + head];
        float4 hv = *(const float4*)&g_h[(size_t)src * FDIM + f];
        for (int i = beg; i < end; i++) {
            int nsrc = 0; float nev = 0.f;
            float4 nhv = make_float4(0.f, 0.f, 0.f, 0.f);
            if (i + 1 < end) {                      // prefetch next edge
                nsrc = g_srcsorted[i + 1];
                nev = g_asrc[nsrc * 2 + head];
                nhv = *(const float4*)&g_h[(size_t)nsrc * FDIM + f];
            }
            float e = ev + ad;
            e = (e > 0.f) ? e : SLOPE * e;
            float nm = fmaxf(m, e);
            float sc = __expf(m - nm);
            float p = __expf(e - nm);
            s = s * sc + p;
            acc.x = acc.x * sc + p * hv.x;
            acc.y = acc.y * sc + p * hv.y;
            acc.z = acc.z * sc + p * hv.z;
            acc.w = acc.w * sc + p * hv.w;
            m = nm;
            ev = nev; hv = nhv;
        }
    }
    float inv = 1.f / (s + 1e-16f);
    float4 o;
    o.x = fmaxf(acc.x * inv + B[f + 0], 0.f);
    o.y = fmaxf(acc.y * inv + B[f + 1], 0.f);
    o.z = fmaxf(acc.z * inv + B[f + 2], 0.f);
    o.w = fmaxf(acc.w * inv + B[f + 3], 0.f);
    *(float4*)&g_x[(size_t)n * FDIM + f] = o;
}

// ---------------- global mean pool (sum + count) ------------------------------
__global__ void pool_kernel(const void* batch) {
    int idx = blockIdx.x * blockDim.x + threadIdx.x;
    int n = idx >> 5;
    int lane = idx & 31;
    if (n >= NNODES) return;
    int b = load_idx(batch, n);
    int f = lane * 4;
    float4 v = *(const float4*)&g_x[(size_t)n * FDIM + f];
    atomicAdd(&g_pool[b * FDIM + f + 0], v.x);
    atomicAdd(&g_pool[b * FDIM + f + 1], v.y);
    atomicAdd(&g_pool[b * FDIM + f + 2], v.z);
    atomicAdd(&g_pool[b * FDIM + f + 3], v.w);
    if (lane == 0) atomicAdd(&g_cnt[b], 1);
}

// ---------------- final linear + sigmoid -------------------------------------
__global__ void final_kernel(const float* __restrict__ LW,
                             const float* __restrict__ LB,
                             float* __restrict__ out) {
    int t = threadIdx.x;
    if (t >= NGRAPH * NCLS) return;
    int g = t / NCLS, c = t % NCLS;
    float cnt = (float)g_cnt[g];
    if (cnt < 1.f) cnt = 1.f;
    float sum = 0.f;
    for (int k = 0; k < FDIM; k++)
        sum = fmaf(g_pool[g * FDIM + k], LW[k * NCLS + c], sum);
    float z = sum / cnt + LB[c];
    out[t] = 1.f / (1.f + expf(-z));
}

// ---------------- launch ------------------------------------------------------
extern "C" void kernel_launch(void* const* d_in, const int* in_sizes, int n_in,
                              void* d_out, int out_size) {
    const float* x = (const float*)d_in[0];
    const void* ei = d_in[1];
    const void* batch = d_in[2];
    const float* W[4]  = {(const float*)d_in[3],  (const float*)d_in[7],
                          (const float*)d_in[11], (const float*)d_in[15]};
    const float* As[4] = {(const float*)d_in[4],  (const float*)d_in[8],
                          (const float*)d_in[12], (const float*)d_in[16]};
    const float* Ad[4] = {(const float*)d_in[5],  (const float*)d_in[9],
                          (const float*)d_in[13], (const float*)d_in[17]};
    const float* Bb[4] = {(const float*)d_in[6],  (const float*)d_in[10],
                          (const float*)d_in[14], (const float*)d_in[18]};
    const float* LW = (const float*)d_in[19];
    const float* LB = (const float*)d_in[20];
    float* out = (float*)d_out;

    detect_kernel<<<1, 256>>>(ei);
    zero_kernel<<<(NNODES + 255) / 256, 256>>>();
    hist_kernel<<<(NEDGES + 255) / 256, 256>>>(ei);
    scanA_kernel<<<NBLK, 256>>>();
    scanB_kernel<<<1, 64>>>();
    scanC_kernel<<<(NNODES + 255) / 256, 256>>>();
    scatter_kernel<<<(NEDGES + 255) / 256, 256>>>(ei);

    int gemm_blocks = (NNODES + 63) / 64;
    int warp_blocks = (NNODES * 32 + 255) / 256;
    for (int l = 0; l < 4; l++) {
        const float* xin = (l == 0) ? x : nullptr;   // nullptr -> use g_x
        int K = (l == 0) ? 4 : FDIM;
        gemm_kernel<<<gemm_blocks, 256>>>(xin, K, W[l], As[l], Ad[l]);
        agg_kernel<<<warp_blocks, 256>>>(Bb[l]);
    }
    pool_kernel<<<warp_blocks, 256>>>(batch);
    final_kernel<<<1, NGRAPH * NCLS>>>(LW, LB, out);
}

// round 5
// speedup vs baseline: 1.6817x; 1.5229x over previous
#include <cuda_runtime.h>
#include <cstdint>

#define NNODES 50000
#define NEDGES 500000
#define NGRAPH 64
#define FDIM   128      // H*D
#define NCLS   5
#define SLOPE  0.2f
#define NBLK   ((NNODES + 1023) / 1024)   // 49 scan blocks

// ---------------- scratch (device globals; no allocations allowed) ----------
__device__ float g_h[(size_t)NNODES * FDIM];
__device__ float g_x[(size_t)NNODES * FDIM];
__device__ float g_asrc[NNODES * 2];
__device__ float g_adst[NNODES * 2];
__device__ int   g_count[NNODES];
__device__ int   g_rowptr[NNODES + 1];
__device__ int   g_pos[NNODES];
__device__ int   g_bsum[64];
__device__ int   g_srcsorted[NEDGES];
__device__ float g_pool[NGRAPH * FDIM];
__device__ int   g_cnt[NGRAPH];
__device__ int   g_is64;

// ---------------- dtype detection (int64 vs int32 indices) ------------------
__global__ void detect_kernel(const void* ei_raw) {
    __shared__ int zeros;
    if (threadIdx.x == 0) zeros = 0;
    __syncthreads();
    const int* w = (const int*)ei_raw;
    int local = 0;
    for (int i = threadIdx.x; i < 1024; i += blockDim.x)
        if (w[2 * i + 1] == 0) local++;
    atomicAdd(&zeros, local);
    __syncthreads();
    if (threadIdx.x == 0) g_is64 = (zeros > 900) ? 1 : 0;
}

__device__ __forceinline__ int load_idx(const void* p, long long i) {
    if (g_is64) return (int)((const long long*)p)[i];
    return ((const int*)p)[i];
}

// ---------------- zero scratch ----------------------------------------------
__global__ void zero_kernel() {
    int i = blockIdx.x * blockDim.x + threadIdx.x;
    if (i < NNODES) g_count[i] = 0;
    if (i < NGRAPH * FDIM) g_pool[i] = 0.f;
    if (i < NGRAPH) g_cnt[i] = 0;
}

// ---------------- CSR build --------------------------------------------------
__global__ void hist_kernel(const void* ei) {
    int e = blockIdx.x * blockDim.x + threadIdx.x;
    if (e >= NEDGES) return;
    int d = load_idx(ei, (long long)NEDGES + e);
    atomicAdd(&g_count[d], 1);
}

__global__ void scanA_kernel() {
    int t = threadIdx.x;
    int base = blockIdx.x * 1024 + t * 4;
    int c0 = 0, c1 = 0, c2 = 0, c3 = 0;
    if (base + 0 < NNODES) c0 = g_count[base + 0];
    if (base + 1 < NNODES) c1 = g_count[base + 1];
    if (base + 2 < NNODES) c2 = g_count[base + 2];
    if (base + 3 < NNODES) c3 = g_count[base + 3];
    int s = c0 + c1 + c2 + c3;
    int lane = t & 31, warp = t >> 5;
    int incl = s;
#pragma unroll
    for (int o = 1; o < 32; o <<= 1) {
        int u = __shfl_up_sync(0xffffffffu, incl, o);
        if (lane >= o) incl += u;
    }
    __shared__ int wtot[8];
    if (lane == 31) wtot[warp] = incl;
    __syncthreads();
    if (t == 0) {
        int r = 0;
#pragma unroll
        for (int w = 0; w < 8; w++) { int v = wtot[w]; wtot[w] = r; r += v; }
        g_bsum[blockIdx.x] = r;
    }
    __syncthreads();
    int excl = incl - s + wtot[warp];
    if (base + 0 < NNODES) g_rowptr[base + 0] = excl;
    if (base + 1 < NNODES) g_rowptr[base + 1] = excl + c0;
    if (base + 2 < NNODES) g_rowptr[base + 2] = excl + c0 + c1;
    if (base + 3 < NNODES) g_rowptr[base + 3] = excl + c0 + c1 + c2;
}

__global__ void scanB_kernel() {
    int t = threadIdx.x;
    int v = (t < NBLK) ? g_bsum[t] : 0;
    int lane = t & 31, warp = t >> 5;
    int incl = v;
#pragma unroll
    for (int o = 1; o < 32; o <<= 1) {
        int u = __shfl_up_sync(0xffffffffu, incl, o);
        if (lane >= o) incl += u;
    }
    __shared__ int wt[2];
    if (lane == 31) wt[warp] = incl;
    __syncthreads();
    int add = (warp == 1) ? wt[0] : 0;
    int excl = incl - v + add;
    if (t < NBLK) g_bsum[t] = excl;
}

__global__ void scanC_kernel() {
    int i = blockIdx.x * blockDim.x + threadIdx.x;
    if (i < NNODES) {
        int r = g_rowptr[i] + g_bsum[i >> 10];
        g_rowptr[i] = r;
        g_pos[i] = r;
    }
    if (i == 0) g_rowptr[NNODES] = NEDGES;
}

__global__ void scatter_kernel(const void* ei) {
    int e = blockIdx.x * blockDim.x + threadIdx.x;
    if (e >= NEDGES) return;
    int s = load_idx(ei, e);
    int d = load_idx(ei, (long long)NEDGES + e);
    int p = atomicAdd(&g_pos[d], 1);
    g_srcsorted[p] = s;
}

// ---------------- tf32 helpers ------------------------------------------------
__device__ __forceinline__ unsigned f2tf32(float x) {
    unsigned r;
    asm("cvt.rna.tf32.f32 %0, %1;" : "=r"(r) : "f"(x));
    return r;
}

__device__ __forceinline__ void mma_tf32(float c[4],
                                         unsigned a0, unsigned a1, unsigned a2, unsigned a3,
                                         unsigned b0, unsigned b1) {
    asm("mma.sync.aligned.m16n8k8.row.col.f32.tf32.tf32.f32 "
        "{%0,%1,%2,%3}, {%4,%5,%6,%7}, {%8,%9}, {%0,%1,%2,%3};"
        : "+f"(c[0]), "+f"(c[1]), "+f"(c[2]), "+f"(c[3])
        : "r"(a0), "r"(a1), "r"(a2), "r"(a3), "r"(b0), "r"(b1));
}

// ---------------- GEMM (tensor core, 3x tf32) + fused attention logits -------
// h = X @ W. Block: 128 nodes x 128 cols, 8 warps; warp w: nodes [w*16, w*16+16).
// 3-pass tf32 error compensation: C += Ah*Bh + Al*Bh + Ah*Bl (err ~ 2e-7).
__global__ __launch_bounds__(256) void gemm_kernel(
    const float* __restrict__ Xin, int K, const float* __restrict__ W,
    const float* __restrict__ Asrc, const float* __restrict__ Adst)
{
    __shared__ float xs[128][8];
    __shared__ float wh[8][136];   // stride 136 -> conflict-free frag loads
    __shared__ float wl[8][136];
    const float* X = Xin ? Xin : g_x;
    int tid = threadIdx.x, lane = tid & 31, warp = tid >> 5;
    int n0 = blockIdx.x * 128;
    int g = lane >> 2, q = lane & 3;

    float acc[16][4];
#pragma unroll
    for (int j = 0; j < 16; j++) { acc[j][0] = acc[j][1] = acc[j][2] = acc[j][3] = 0.f; }

    for (int k0 = 0; k0 < K; k0 += 8) {
        // stage X tile [128 x 8]
        {
            int r = tid >> 1, c4 = (tid & 1) * 4;
            int n = n0 + r;
            float4 xv = make_float4(0.f, 0.f, 0.f, 0.f);
            if (n < NNODES) {
                if (k0 + c4 + 3 < K) {
                    xv = *(const float4*)&X[(size_t)n * K + k0 + c4];
                } else {
#pragma unroll
                    for (int u = 0; u < 4; u++) {
                        int k = k0 + c4 + u;
                        if (k < K) ((float*)&xv)[u] = X[(size_t)n * K + k];
                    }
                }
            }
            xs[r][c4 + 0] = xv.x; xs[r][c4 + 1] = xv.y;
            xs[r][c4 + 2] = xv.z; xs[r][c4 + 3] = xv.w;
        }
        // stage W tile [8 x 128] pre-split into tf32 hi/lo
        {
            int kr = tid >> 5, wc = (tid & 31) * 4;
            float4 wv = make_float4(0.f, 0.f, 0.f, 0.f);
            if (k0 + kr < K) wv = *(const float4*)&W[(size_t)(k0 + kr) * FDIM + wc];
#pragma unroll
            for (int u = 0; u < 4; u++) {
                float v = ((float*)&wv)[u];
                unsigned h = f2tf32(v);
                unsigned l = f2tf32(v - __uint_as_float(h));
                wh[kr][wc + u] = __uint_as_float(h);
                wl[kr][wc + u] = __uint_as_float(l);
            }
        }
        __syncthreads();

        // A fragments (m16k8, row-major) with in-register hi/lo split
        int ra = warp * 16 + g;
        float a00 = xs[ra][q],     a10 = xs[ra + 8][q];
        float a01 = xs[ra][q + 4], a11 = xs[ra + 8][q + 4];
        unsigned ah0 = f2tf32(a00), ah1 = f2tf32(a10), ah2 = f2tf32(a01), ah3 = f2tf32(a11);
        unsigned al0 = f2tf32(a00 - __uint_as_float(ah0));
        unsigned al1 = f2tf32(a10 - __uint_as_float(ah1));
        unsigned al2 = f2tf32(a01 - __uint_as_float(ah2));
        unsigned al3 = f2tf32(a11 - __uint_as_float(ah3));

#pragma unroll
        for (int j = 0; j < 16; j++) {
            unsigned bh0 = __float_as_uint(wh[q][j * 8 + g]);
            unsigned bh1 = __float_as_uint(wh[q + 4][j * 8 + g]);
            unsigned bl0 = __float_as_uint(wl[q][j * 8 + g]);
            unsigned bl1 = __float_as_uint(wl[q + 4][j * 8 + g]);
            mma_tf32(acc[j], ah0, ah1, ah2, ah3, bh0, bh1);
            mma_tf32(acc[j], al0, al1, al2, al3, bh0, bh1);
            mma_tf32(acc[j], ah0, ah1, ah2, ah3, bl0, bl1);
        }
        __syncthreads();
    }

    // epilogue: store h + fused alpha logits
    int nr0 = n0 + warp * 16 + g;
    int nr1 = nr0 + 8;
    float vs0[2] = {0.f, 0.f}, vd0[2] = {0.f, 0.f};
    float vs1[2] = {0.f, 0.f}, vd1[2] = {0.f, 0.f};
#pragma unroll
    for (int j = 0; j < 16; j++) {
        int jc = j * 8 + 2 * q;
        int hd = j >> 3;
        float as0 = Asrc[jc], as1 = Asrc[jc + 1];
        float ad0 = Adst[jc], ad1 = Adst[jc + 1];
        if (nr0 < NNODES)
            *(float2*)&g_h[(size_t)nr0 * FDIM + jc] = make_float2(acc[j][0], acc[j][1]);
        if (nr1 < NNODES)
            *(float2*)&g_h[(size_t)nr1 * FDIM + jc] = make_float2(acc[j][2], acc[j][3]);
        vs0[hd] += acc[j][0] * as0 + acc[j][1] * as1;
        vd0[hd] += acc[j][0] * ad0 + acc[j][1] * ad1;
        vs1[hd] += acc[j][2] * as0 + acc[j][3] * as1;
        vd1[hd] += acc[j][2] * ad0 + acc[j][3] * ad1;
    }
#pragma unroll
    for (int o = 1; o < 4; o <<= 1) {
        vs0[0] += __shfl_xor_sync(0xffffffffu, vs0[0], o);
        vs0[1] += __shfl_xor_sync(0xffffffffu, vs0[1], o);
        vd0[0] += __shfl_xor_sync(0xffffffffu, vd0[0], o);
        vd0[1] += __shfl_xor_sync(0xffffffffu, vd0[1], o);
        vs1[0] += __shfl_xor_sync(0xffffffffu, vs1[0], o);
        vs1[1] += __shfl_xor_sync(0xffffffffu, vs1[1], o);
        vd1[0] += __shfl_xor_sync(0xffffffffu, vd1[0], o);
        vd1[1] += __shfl_xor_sync(0xffffffffu, vd1[1], o);
    }
    if (q == 0) {
        if (nr0 < NNODES) {
            g_asrc[nr0 * 2 + 0] = vs0[0]; g_asrc[nr0 * 2 + 1] = vs0[1];
            g_adst[nr0 * 2 + 0] = vd0[0]; g_adst[nr0 * 2 + 1] = vd0[1];
        }
        if (nr1 < NNODES) {
            g_asrc[nr1 * 2 + 0] = vs1[0]; g_asrc[nr1 * 2 + 1] = vs1[1];
            g_adst[nr1 * 2 + 0] = vd1[0]; g_adst[nr1 * 2 + 1] = vd1[1];
        }
    }
}

// ---------------- aggregation: online segment softmax + weighted sum ---------
__global__ void agg_kernel(const float* __restrict__ B) {
    int n = (blockIdx.x * blockDim.x + threadIdx.x) >> 5;
    int lane = threadIdx.x & 31;
    if (n >= NNODES) return;
    int f = lane * 4;
    int head = lane >> 4;
    float ad = g_adst[n * 2 + head];
    int beg = g_rowptr[n], end = g_rowptr[n + 1];

    float m = -3.0e38f, s = 0.f;
    float4 acc = make_float4(0.f, 0.f, 0.f, 0.f);
    if (beg < end) {
        int src = g_srcsorted[beg];
        float ev = g_asrc[src * 2 + head];
        float4 hv = *(const float4*)&g_h[(size_t)src * FDIM + f];
        for (int i = beg; i < end; i++) {
            int nsrc = 0; float nev = 0.f;
            float4 nhv = make_float4(0.f, 0.f, 0.f, 0.f);
            if (i + 1 < end) {
                nsrc = g_srcsorted[i + 1];
                nev = g_asrc[nsrc * 2 + head];
                nhv = *(const float4*)&g_h[(size_t)nsrc * FDIM + f];
            }
            float e = ev + ad;
            e = (e > 0.f) ? e : SLOPE * e;
            float nm = fmaxf(m, e);
            float sc = __expf(m - nm);
            float p = __expf(e - nm);
            s = s * sc + p;
            acc.x = acc.x * sc + p * hv.x;
            acc.y = acc.y * sc + p * hv.y;
            acc.z = acc.z * sc + p * hv.z;
            acc.w = acc.w * sc + p * hv.w;
            m = nm;
            ev = nev; hv = nhv;
        }
    }
    float inv = 1.f / (s + 1e-16f);
    float4 o;
    o.x = fmaxf(acc.x * inv + B[f + 0], 0.f);
    o.y = fmaxf(acc.y * inv + B[f + 1], 0.f);
    o.z = fmaxf(acc.z * inv + B[f + 2], 0.f);
    o.w = fmaxf(acc.w * inv + B[f + 3], 0.f);
    *(float4*)&g_x[(size_t)n * FDIM + f] = o;
}

// ---------------- global mean pool (smem-reduced atomics) ---------------------
// 8 nodes/block; batch is sorted so blocks are almost always single-graph.
__global__ void pool_kernel(const void* batch) {
    __shared__ float s[8][128];
    __shared__ int sb[8];
    int tid = threadIdx.x, warp = tid >> 5, lane = tid & 31;
    int n = blockIdx.x * 8 + warp;        // NNODES % 8 == 0: always valid
    int b = load_idx(batch, n);
    if (lane == 0) sb[warp] = b;
    int f = lane * 4;
    float4 v = *(const float4*)&g_x[(size_t)n * FDIM + f];
    *(float4*)&s[warp][f] = v;
    __syncthreads();
    bool uni = true;
#pragma unroll
    for (int w = 1; w < 8; w++) uni &= (sb[w] == sb[0]);
    if (uni) {
        if (tid < 128) {
            float sum = 0.f;
#pragma unroll
            for (int w = 0; w < 8; w++) sum += s[w][tid];
            atomicAdd(&g_pool[sb[0] * FDIM + tid], sum);
        }
        if (tid == 0) atomicAdd(&g_cnt[sb[0]], 8);
    } else {
        atomicAdd(&g_pool[b * FDIM + f + 0], v.x);
        atomicAdd(&g_pool[b * FDIM + f + 1], v.y);
        atomicAdd(&g_pool[b * FDIM + f + 2], v.z);
        atomicAdd(&g_pool[b * FDIM + f + 3], v.w);
        if (lane == 0) atomicAdd(&g_cnt[b], 1);
    }
}

// ---------------- final linear + sigmoid -------------------------------------
__global__ void final_kernel(const float* __restrict__ LW,
                             const float* __restrict__ LB,
                             float* __restrict__ out) {
    int t = threadIdx.x;
    if (t >= NGRAPH * NCLS) return;
    int g = t / NCLS, c = t % NCLS;
    float cnt = (float)g_cnt[g];
    if (cnt < 1.f) cnt = 1.f;
    float sum = 0.f;
    for (int k = 0; k < FDIM; k++)
        sum = fmaf(g_pool[g * FDIM + k], LW[k * NCLS + c], sum);
    float z = sum / cnt + LB[c];
    out[t] = 1.f / (1.f + expf(-z));
}

// ---------------- launch ------------------------------------------------------
extern "C" void kernel_launch(void* const* d_in, const int* in_sizes, int n_in,
                              void* d_out, int out_size) {
    const float* x = (const float*)d_in[0];
    const void* ei = d_in[1];
    const void* batch = d_in[2];
    const float* W[4]  = {(const float*)d_in[3],  (const float*)d_in[7],
                          (const float*)d_in[11], (const float*)d_in[15]};
    const float* As[4] = {(const float*)d_in[4],  (const float*)d_in[8],
                          (const float*)d_in[12], (const float*)d_in[16]};
    const float* Ad[4] = {(const float*)d_in[5],  (const float*)d_in[9],
                          (const float*)d_in[13], (const float*)d_in[17]};
    const float* Bb[4] = {(const float*)d_in[6],  (const float*)d_in[10],
                          (const float*)d_in[14], (const float*)d_in[18]};
    const float* LW = (const float*)d_in[19];
    const float* LB = (const float*)d_in[20];
    float* out = (float*)d_out;

    detect_kernel<<<1, 256>>>(ei);
    zero_kernel<<<(NNODES + 255) / 256, 256>>>();
    hist_kernel<<<(NEDGES + 255) / 256, 256>>>(ei);
    scanA_kernel<<<NBLK, 256>>>();
    scanB_kernel<<<1, 64>>>();
    scanC_kernel<<<(NNODES + 255) / 256, 256>>>();
    scatter_kernel<<<(NEDGES + 255) / 256, 256>>>(ei);

    int gemm_blocks = (NNODES + 127) / 128;
    int warp_blocks = (NNODES * 32 + 255) / 256;
    for (int l = 0; l < 4; l++) {
        const float* xin = (l == 0) ? x : nullptr;   // nullptr -> use g_x
        int K = (l == 0) ? 4 : FDIM;
        gemm_kernel<<<gemm_blocks, 256>>>(xin, K, W[l], As[l], Ad[l]);
        agg_kernel<<<warp_blocks, 256>>>(Bb[l]);
    }
    pool_kernel<<<(NNODES / 8), 256>>>(batch);
    final_kernel<<<1, NGRAPH * NCLS>>>(LW, LB, out);
}

// round 6
// speedup vs baseline: 1.7639x; 1.0489x over previous
#include <cuda_runtime.h>
#include <cuda_fp16.h>
#include <cstdint>

#define NNODES 50000
#define NEDGES 500000
#define NGRAPH 64
#define FDIM   128      // H*D
#define NCLS   5
#define SLOPE  0.2f
#define NBLK   ((NNODES + 1023) / 1024)   // 49 scan blocks

// ---------------- scratch (device globals; no allocations allowed) ----------
__device__ __half g_hh[(size_t)NNODES * FDIM];   // fp16 h for gather path
__device__ float g_x[(size_t)NNODES * FDIM];     // fp32 layer input
__device__ float g_asrc[NNODES * 2];
__device__ float g_adst[NNODES * 2];
__device__ int   g_count[NNODES];
__device__ int   g_rowptr[NNODES + 1];
__device__ int   g_pos[NNODES];
__device__ int   g_bsum[64];
__device__ int   g_srcsorted[NEDGES];
__device__ float g_pool[NGRAPH * FDIM];
__device__ int   g_cnt[NGRAPH];
__device__ int   g_is64;

__device__ __forceinline__ int load_idx(const void* p, long long i) {
    if (g_is64) return (int)((const long long*)p)[i];
    return ((const int*)p)[i];
}

// ---------------- zero scratch + dtype detection (merged) --------------------
__global__ void zero_kernel(const void* ei_raw) {
    int i = blockIdx.x * blockDim.x + threadIdx.x;
    if (i < NNODES) g_count[i] = 0;
    if (i < NGRAPH * FDIM) g_pool[i] = 0.f;
    if (i < NGRAPH) g_cnt[i] = 0;
    if (blockIdx.x == 0) {
        // int64 detection: odd 32-bit words are 0 iff values are small int64.
        __shared__ int zeros;
        if (threadIdx.x == 0) zeros = 0;
        __syncthreads();
        const int* w = (const int*)ei_raw;
        int local = 0;
        for (int k = threadIdx.x; k < 1024; k += blockDim.x)
            if (w[2 * k + 1] == 0) local++;
        atomicAdd(&zeros, local);
        __syncthreads();
        if (threadIdx.x == 0) g_is64 = (zeros > 900) ? 1 : 0;
    }
}

// ---------------- CSR build --------------------------------------------------
__global__ void hist_kernel(const void* ei) {
    int e = blockIdx.x * blockDim.x + threadIdx.x;
    if (e >= NEDGES) return;
    int d = load_idx(ei, (long long)NEDGES + e);
    atomicAdd(&g_count[d], 1);
}

__global__ void scanA_kernel() {
    int t = threadIdx.x;
    int base = blockIdx.x * 1024 + t * 4;
    int c0 = 0, c1 = 0, c2 = 0, c3 = 0;
    if (base + 0 < NNODES) c0 = g_count[base + 0];
    if (base + 1 < NNODES) c1 = g_count[base + 1];
    if (base + 2 < NNODES) c2 = g_count[base + 2];
    if (base + 3 < NNODES) c3 = g_count[base + 3];
    int s = c0 + c1 + c2 + c3;
    int lane = t & 31, warp = t >> 5;
    int incl = s;
#pragma unroll
    for (int o = 1; o < 32; o <<= 1) {
        int u = __shfl_up_sync(0xffffffffu, incl, o);
        if (lane >= o) incl += u;
    }
    __shared__ int wtot[8];
    if (lane == 31) wtot[warp] = incl;
    __syncthreads();
    if (t == 0) {
        int r = 0;
#pragma unroll
        for (int w = 0; w < 8; w++) { int v = wtot[w]; wtot[w] = r; r += v; }
        g_bsum[blockIdx.x] = r;
    }
    __syncthreads();
    int excl = incl - s + wtot[warp];
    if (base + 0 < NNODES) g_rowptr[base + 0] = excl;
    if (base + 1 < NNODES) g_rowptr[base + 1] = excl + c0;
    if (base + 2 < NNODES) g_rowptr[base + 2] = excl + c0 + c1;
    if (base + 3 < NNODES) g_rowptr[base + 3] = excl + c0 + c1 + c2;
}

__global__ void scanB_kernel() {
    int t = threadIdx.x;
    int v = (t < NBLK) ? g_bsum[t] : 0;
    int lane = t & 31, warp = t >> 5;
    int incl = v;
#pragma unroll
    for (int o = 1; o < 32; o <<= 1) {
        int u = __shfl_up_sync(0xffffffffu, incl, o);
        if (lane >= o) incl += u;
    }
    __shared__ int wt[2];
    if (lane == 31) wt[warp] = incl;
    __syncthreads();
    int add = (warp == 1) ? wt[0] : 0;
    int excl = incl - v + add;
    if (t < NBLK) g_bsum[t] = excl;
}

__global__ void scanC_kernel() {
    int i = blockIdx.x * blockDim.x + threadIdx.x;
    if (i < NNODES) {
        int r = g_rowptr[i] + g_bsum[i >> 10];
        g_rowptr[i] = r;
        g_pos[i] = r;
    }
    if (i == 0) g_rowptr[NNODES] = NEDGES;
}

__global__ void scatter_kernel(const void* ei) {
    int e = blockIdx.x * blockDim.x + threadIdx.x;
    if (e >= NEDGES) return;
    int s = load_idx(ei, e);
    int d = load_idx(ei, (long long)NEDGES + e);
    int p = atomicAdd(&g_pos[d], 1);
    g_srcsorted[p] = s;
}

// ---------------- tf32 helpers ------------------------------------------------
__device__ __forceinline__ unsigned f2tf32(float x) {
    unsigned r;
    asm("cvt.rna.tf32.f32 %0, %1;" : "=r"(r) : "f"(x));
    return r;
}

__device__ __forceinline__ void mma_tf32(float c[4],
                                         unsigned a0, unsigned a1, unsigned a2, unsigned a3,
                                         unsigned b0, unsigned b1) {
    asm("mma.sync.aligned.m16n8k8.row.col.f32.tf32.tf32.f32 "
        "{%0,%1,%2,%3}, {%4,%5,%6,%7}, {%8,%9}, {%0,%1,%2,%3};"
        : "+f"(c[0]), "+f"(c[1]), "+f"(c[2]), "+f"(c[3])
        : "r"(a0), "r"(a1), "r"(a2), "r"(a3), "r"(b0), "r"(b1));
}

// ---------------- GEMM (tensor core, 3x tf32) + fused attention logits -------
// h = X @ W. Block: 128 nodes x 128 cols, 8 warps. Logits fp32; h stored fp16.
__global__ __launch_bounds__(256) void gemm_kernel(
    const float* __restrict__ Xin, int K, const float* __restrict__ W,
    const float* __restrict__ Asrc, const float* __restrict__ Adst)
{
    __shared__ float xs[128][8];
    __shared__ float wh[8][136];
    __shared__ float wl[8][136];
    const float* X = Xin ? Xin : g_x;
    int tid = threadIdx.x, lane = tid & 31, warp = tid >> 5;
    int n0 = blockIdx.x * 128;
    int g = lane >> 2, q = lane & 3;

    float acc[16][4];
#pragma unroll
    for (int j = 0; j < 16; j++) { acc[j][0] = acc[j][1] = acc[j][2] = acc[j][3] = 0.f; }

    for (int k0 = 0; k0 < K; k0 += 8) {
        {
            int r = tid >> 1, c4 = (tid & 1) * 4;
            int n = n0 + r;
            float4 xv = make_float4(0.f, 0.f, 0.f, 0.f);
            if (n < NNODES) {
                if (k0 + c4 + 3 < K) {
                    xv = *(const float4*)&X[(size_t)n * K + k0 + c4];
                } else {
#pragma unroll
                    for (int u = 0; u < 4; u++) {
                        int k = k0 + c4 + u;
                        if (k < K) ((float*)&xv)[u] = X[(size_t)n * K + k];
                    }
                }
            }
            xs[r][c4 + 0] = xv.x; xs[r][c4 + 1] = xv.y;
            xs[r][c4 + 2] = xv.z; xs[r][c4 + 3] = xv.w;
        }
        {
            int kr = tid >> 5, wc = (tid & 31) * 4;
            float4 wv = make_float4(0.f, 0.f, 0.f, 0.f);
            if (k0 + kr < K) wv = *(const float4*)&W[(size_t)(k0 + kr) * FDIM + wc];
#pragma unroll
            for (int u = 0; u < 4; u++) {
                float v = ((float*)&wv)[u];
                unsigned h = f2tf32(v);
                unsigned l = f2tf32(v - __uint_as_float(h));
                wh[kr][wc + u] = __uint_as_float(h);
                wl[kr][wc + u] = __uint_as_float(l);
            }
        }
        __syncthreads();

        int ra = warp * 16 + g;
        float a00 = xs[ra][q],     a10 = xs[ra + 8][q];
        float a01 = xs[ra][q + 4], a11 = xs[ra + 8][q + 4];
        unsigned ah0 = f2tf32(a00), ah1 = f2tf32(a10), ah2 = f2tf32(a01), ah3 = f2tf32(a11);
        unsigned al0 = f2tf32(a00 - __uint_as_float(ah0));
        unsigned al1 = f2tf32(a10 - __uint_as_float(ah1));
        unsigned al2 = f2tf32(a01 - __uint_as_float(ah2));
        unsigned al3 = f2tf32(a11 - __uint_as_float(ah3));

#pragma unroll
        for (int j = 0; j < 16; j++) {
            unsigned bh0 = __float_as_uint(wh[q][j * 8 + g]);
            unsigned bh1 = __float_as_uint(wh[q + 4][j * 8 + g]);
            unsigned bl0 = __float_as_uint(wl[q][j * 8 + g]);
            unsigned bl1 = __float_as_uint(wl[q + 4][j * 8 + g]);
            mma_tf32(acc[j], ah0, ah1, ah2, ah3, bh0, bh1);
            mma_tf32(acc[j], al0, al1, al2, al3, bh0, bh1);
            mma_tf32(acc[j], ah0, ah1, ah2, ah3, bl0, bl1);
        }
        __syncthreads();
    }

    // epilogue: store h (fp16) + fused fp32 alpha logits
    int nr0 = n0 + warp * 16 + g;
    int nr1 = nr0 + 8;
    float vs0[2] = {0.f, 0.f}, vd0[2] = {0.f, 0.f};
    float vs1[2] = {0.f, 0.f}, vd1[2] = {0.f, 0.f};
#pragma unroll
    for (int j = 0; j < 16; j++) {
        int jc = j * 8 + 2 * q;
        int hd = j >> 3;
        float as0 = Asrc[jc], as1 = Asrc[jc + 1];
        float ad0 = Adst[jc], ad1 = Adst[jc + 1];
        if (nr0 < NNODES)
            *(__half2*)&g_hh[(size_t)nr0 * FDIM + jc] = __floats2half2_rn(acc[j][0], acc[j][1]);
        if (nr1 < NNODES)
            *(__half2*)&g_hh[(size_t)nr1 * FDIM + jc] = __floats2half2_rn(acc[j][2], acc[j][3]);
        vs0[hd] += acc[j][0] * as0 + acc[j][1] * as1;
        vd0[hd] += acc[j][0] * ad0 + acc[j][1] * ad1;
        vs1[hd] += acc[j][2] * as0 + acc[j][3] * as1;
        vd1[hd] += acc[j][2] * ad0 + acc[j][3] * ad1;
    }
#pragma unroll
    for (int o = 1; o < 4; o <<= 1) {
        vs0[0] += __shfl_xor_sync(0xffffffffu, vs0[0], o);
        vs0[1] += __shfl_xor_sync(0xffffffffu, vs0[1], o);
        vd0[0] += __shfl_xor_sync(0xffffffffu, vd0[0], o);
        vd0[1] += __shfl_xor_sync(0xffffffffu, vd0[1], o);
        vs1[0] += __shfl_xor_sync(0xffffffffu, vs1[0], o);
        vs1[1] += __shfl_xor_sync(0xffffffffu, vs1[1], o);
        vd1[0] += __shfl_xor_sync(0xffffffffu, vd1[0], o);
        vd1[1] += __shfl_xor_sync(0xffffffffu, vd1[1], o);
    }
    if (q == 0) {
        if (nr0 < NNODES) {
            g_asrc[nr0 * 2 + 0] = vs0[0]; g_asrc[nr0 * 2 + 1] = vs0[1];
            g_adst[nr0 * 2 + 0] = vd0[0]; g_adst[nr0 * 2 + 1] = vd0[1];
        }
        if (nr1 < NNODES) {
            g_asrc[nr1 * 2 + 0] = vs1[0]; g_asrc[nr1 * 2 + 1] = vs1[1];
            g_adst[nr1 * 2 + 0] = vd1[0]; g_adst[nr1 * 2 + 1] = vd1[1];
        }
    }
}

// ---------------- aggregation: online softmax, fp16 gather, depth-2 prefetch --
// One warp per dst node; lanes 0-15 head 0, 16-31 head 1. Optionally fuses the
// final-layer mean-pool (blocks cover 8 consecutive nodes).
__global__ void agg_kernel(const float* __restrict__ B,
                           const void* batch, int dopool) {
    __shared__ float sm[8][128];
    __shared__ int sb[8];
    int tid = threadIdx.x;
    int n = (blockIdx.x * blockDim.x + tid) >> 5;
    int lane = tid & 31, warp = tid >> 5;
    if (n >= NNODES) return;
    int f = lane * 4;
    int head = lane >> 4;
    float ad = g_adst[n * 2 + head];
    int beg = g_rowptr[n], end = g_rowptr[n + 1];

    float m = -3.0e38f, s = 0.f;
    float4 acc = make_float4(0.f, 0.f, 0.f, 0.f);
    float ev0 = 0.f, ev1 = 0.f;
    uint2 rv0 = make_uint2(0, 0), rv1 = make_uint2(0, 0);
    if (beg < end) {
        int s0 = g_srcsorted[beg];
        ev0 = g_asrc[s0 * 2 + head];
        rv0 = *(const uint2*)&g_hh[(size_t)s0 * FDIM + f];
    }
    if (beg + 1 < end) {
        int s1 = g_srcsorted[beg + 1];
        ev1 = g_asrc[s1 * 2 + head];
        rv1 = *(const uint2*)&g_hh[(size_t)s1 * FDIM + f];
    }
    for (int i = beg; i < end; i++) {
        float ev2 = 0.f; uint2 rv2 = make_uint2(0, 0);
        if (i + 2 < end) {
            int s2 = g_srcsorted[i + 2];
            ev2 = g_asrc[s2 * 2 + head];
            rv2 = *(const uint2*)&g_hh[(size_t)s2 * FDIM + f];
        }
        float e = ev0 + ad;
        e = (e > 0.f) ? e : SLOPE * e;
        float nm = fmaxf(m, e);
        float sc = __expf(m - nm);
        float p = __expf(e - nm);
        s = s * sc + p;
        float2 fA = __half22float2(*(__half2*)&rv0.x);
        float2 fB = __half22float2(*(__half2*)&rv0.y);
        acc.x = acc.x * sc + p * fA.x;
        acc.y = acc.y * sc + p * fA.y;
        acc.z = acc.z * sc + p * fB.x;
        acc.w = acc.w * sc + p * fB.y;
        m = nm;
        ev0 = ev1; rv0 = rv1; ev1 = ev2; rv1 = rv2;
    }
    float inv = 1.f / (s + 1e-16f);
    float4 o;
    o.x = fmaxf(acc.x * inv + B[f + 0], 0.f);
    o.y = fmaxf(acc.y * inv + B[f + 1], 0.f);
    o.z = fmaxf(acc.z * inv + B[f + 2], 0.f);
    o.w = fmaxf(acc.w * inv + B[f + 3], 0.f);

    if (!dopool) {
        *(float4*)&g_x[(size_t)n * FDIM + f] = o;
    } else {
        // fused mean-pool accumulation (batch sorted -> blocks ~single-graph)
        int b = load_idx(batch, n);
        if (lane == 0) sb[warp] = b;
        *(float4*)&sm[warp][f] = o;
        __syncthreads();
        bool uni = true;
#pragma unroll
        for (int w = 1; w < 8; w++) uni &= (sb[w] == sb[0]);
        if (uni) {
            if (tid < 128) {
                float sum = 0.f;
#pragma unroll
                for (int w = 0; w < 8; w++) sum += sm[w][tid];
                atomicAdd(&g_pool[sb[0] * FDIM + tid], sum);
            }
            if (tid == 0) atomicAdd(&g_cnt[sb[0]], 8);
        } else {
            atomicAdd(&g_pool[b * FDIM + f + 0], o.x);
            atomicAdd(&g_pool[b * FDIM + f + 1], o.y);
            atomicAdd(&g_pool[b * FDIM + f + 2], o.z);
            atomicAdd(&g_pool[b * FDIM + f + 3], o.w);
            if (lane == 0) atomicAdd(&g_cnt[b], 1);
        }
    }
}

// ---------------- final linear + sigmoid -------------------------------------
__global__ void final_kernel(const float* __restrict__ LW,
                             const float* __restrict__ LB,
                             float* __restrict__ out) {
    int t = threadIdx.x;
    if (t >= NGRAPH * NCLS) return;
    int g = t / NCLS, c = t % NCLS;
    float cnt = (float)g_cnt[g];
    if (cnt < 1.f) cnt = 1.f;
    float sum = 0.f;
    for (int k = 0; k < FDIM; k++)
        sum = fmaf(g_pool[g * FDIM + k], LW[k * NCLS + c], sum);
    float z = sum / cnt + LB[c];
    out[t] = 1.f / (1.f + expf(-z));
}

// ---------------- launch ------------------------------------------------------
extern "C" void kernel_launch(void* const* d_in, const int* in_sizes, int n_in,
                              void* d_out, int out_size) {
    const float* x = (const float*)d_in[0];
    const void* ei = d_in[1];
    const void* batch = d_in[2];
    const float* W[4]  = {(const float*)d_in[3],  (const float*)d_in[7],
                          (const float*)d_in[11], (const float*)d_in[15]};
    const float* As[4] = {(const float*)d_in[4],  (const float*)d_in[8],
                          (const float*)d_in[12], (const float*)d_in[16]};
    const float* Ad[4] = {(const float*)d_in[5],  (const float*)d_in[9],
                          (const float*)d_in[13], (const float*)d_in[17]};
    const float* Bb[4] = {(const float*)d_in[6],  (const float*)d_in[10],
                          (const float*)d_in[14], (const float*)d_in[18]};
    const float* LW = (const float*)d_in[19];
    const float* LB = (const float*)d_in[20];
    float* out = (float*)d_out;

    zero_kernel<<<(NNODES + 255) / 256, 256>>>(ei);
    hist_kernel<<<(NEDGES + 255) / 256, 256>>>(ei);
    scanA_kernel<<<NBLK, 256>>>();
    scanB_kernel<<<1, 64>>>();
    scanC_kernel<<<(NNODES + 255) / 256, 256>>>();
    scatter_kernel<<<(NEDGES + 255) / 256, 256>>>(ei);

    int gemm_blocks = (NNODES + 127) / 128;
    int warp_blocks = (NNODES * 32 + 255) / 256;
    for (int l = 0; l < 4; l++) {
        const float* xin = (l == 0) ? x : nullptr;   // nullptr -> use g_x
        int K = (l == 0) ? 4 : FDIM;
        gemm_kernel<<<gemm_blocks, 256>>>(xin, K, W[l], As[l], Ad[l]);
        agg_kernel<<<warp_blocks, 256>>>(Bb[l], batch, (l == 3) ? 1 : 0);
    }
    final_kernel<<<1, NGRAPH * NCLS>>>(LW, LB, out);
}